// round 14
// baseline (speedup 1.0000x reference)
#include <cuda_runtime.h>
#include <cuda_fp16.h>
#include <cstdint>
#include <math.h>

#define BATCH 32
#define SEQ   512
#define DIM   512

// ---------------- scratch (static device memory; no allocations) ------------
#define NELEM ((size_t)BATCH * SEQ * DIM)          // 8,388,608
#define WELEM ((size_t)DIM * 2 * DIM)              // 524,288
__device__ __align__(16) __half g_qh[NELEM];                // Q fp16       [b,q,d]
__device__ __align__(16) __half g_eh[NELEM];                // Enc fp16     [b,e,d]
__device__ __align__(16) __half g_awh[NELEM];               // attn weights [b,q,e]
__device__ __align__(16) __half g_ch[NELEM];                // ctx fp16     [b,q,d]
__device__ __align__(16) __half g_wh[WELEM];                // W fp16

// ---------------- PTX helpers (all non-arch-'a'; compile for sm_103) --------
__device__ __forceinline__ uint32_t smem_u32(const void* p) {
    uint32_t a;
    asm("{ .reg .u64 t; cvta.to.shared.u64 t, %1; cvt.u32.u64 %0, t; }" : "=r"(a) : "l"(p));
    return a;
}
__device__ __forceinline__ void cp16(uint32_t dst, const void* src) {
    asm volatile("cp.async.cg.shared.global [%0], [%1], 16;" :: "r"(dst), "l"(src));
}
#define CP_COMMIT() asm volatile("cp.async.commit_group;" ::: "memory")
#define CP_WAIT1()  asm volatile("cp.async.wait_group 1;" ::: "memory")

__device__ __forceinline__ void ldm4(uint32_t* r, uint32_t addr) {
    asm volatile("ldmatrix.sync.aligned.m8n8.x4.shared.b16 {%0,%1,%2,%3}, [%4];"
                 : "=r"(r[0]), "=r"(r[1]), "=r"(r[2]), "=r"(r[3]) : "r"(addr));
}
__device__ __forceinline__ void ldm4t(uint32_t* r, uint32_t addr) {
    asm volatile("ldmatrix.sync.aligned.m8n8.x4.trans.shared.b16 {%0,%1,%2,%3}, [%4];"
                 : "=r"(r[0]), "=r"(r[1]), "=r"(r[2]), "=r"(r[3]) : "r"(addr));
}
__device__ __forceinline__ void mma16816(float* c, const uint32_t* a, const uint32_t* b) {
    asm volatile(
        "mma.sync.aligned.m16n8k16.row.col.f32.f16.f16.f32 "
        "{%0,%1,%2,%3}, {%4,%5,%6,%7}, {%8,%9}, {%0,%1,%2,%3};"
        : "+f"(c[0]), "+f"(c[1]), "+f"(c[2]), "+f"(c[3])
        : "r"(a[0]), "r"(a[1]), "r"(a[2]), "r"(a[3]), "r"(b[0]), "r"(b[1]));
}

// ---------------- GEMM: C = A @ B^T, fp16 1-term -----------------------------
// CTA tile 128(m) x 128(n), BK=32. 8 warps = 2m x 4n, warp tile 64x32
// (ratio mn/(8(m+n)) = 2.67 MMA/ldmatrix vs 2.0 for 32x32).
// smem/stage: A 8KB + B 8KB = 16KB; 3 stages = 48KB; 2 CTAs/SM (regs ~105).
#define TILE_A   8192           // 128 rows x 64B
#define TILE_BB  8192           // 128 rows x 64B (or 32 rows x 256B for MODE1)
#define OFFBH    TILE_A
#define STAGEB   (TILE_A + TILE_BB)   // 16KB
#define NSTAGE   3
#define SMEM_DYN (NSTAGE * STAGEB)
#define SB ((size_t)SEQ * DIM)

// swizzled byte offset within one NT tile for (row, 16B-chunk kc), 64B rows
__device__ __forceinline__ uint32_t swz(int row, int kc) {
    return (uint32_t)(row * 64 + ((kc ^ ((row >> 1) & 3)) << 4));
}

// MODE 0: scores = alpha * Q @ Enc^T          -> Cf (fp32)
// MODE 1: ctx    = AW @ Enc  (trans-B)        -> g_ch (fp16)
// MODE 2: out    = tanh([Q|ctx] @ W^T + b)*m  -> Cf (fp32)
template <int MODE>
__global__ __launch_bounds__(256, 2) void k_gemm(
    float* __restrict__ Cf, const float* __restrict__ bias,
    const float* __restrict__ mask, float alpha)
{
    extern __shared__ char smem[];
    const uint32_t sm = smem_u32(smem);

    const int tid = threadIdx.x;
    const int lane = tid & 31, wid = tid >> 5;
    const int wm = wid & 1, wn = wid >> 1;       // 2 m-warps x 4 n-warps
    const int b  = blockIdx.z;
    const int m0 = blockIdx.y * 128;
    const int n0 = blockIdx.x * 128;

    const __half *Ah, *A2h = nullptr, *Bh;
    int K, lda, ldb;
    if (MODE == 0) {
        Ah = g_qh + (size_t)b * SB;
        Bh = g_eh + (size_t)b * SB;
        K = DIM; lda = DIM; ldb = DIM;
    } else if (MODE == 1) {
        Ah = g_awh + (size_t)b * SB;
        Bh = g_eh + (size_t)b * SB;                                // [e][d] plain
        K = SEQ; lda = SEQ; ldb = DIM;
    } else {
        Ah = g_qh;  A2h = g_ch;      // rows indexed by global m (0..16383)
        Bh = g_wh;
        K = 2 * DIM; lda = DIM; ldb = 2 * DIM;
    }
    const int C = K >> 5;   // chunks of 32

#define LOAD_CHUNK(c, stg)                                                       \
    do {                                                                         \
        const int k0_ = (c) * 32;                                                \
        const __half* ah_; int ka_;                                              \
        if (MODE == 2 && k0_ >= DIM) { ah_ = A2h; ka_ = k0_ - DIM; }             \
        else                         { ah_ = Ah;  ka_ = k0_; }                   \
        const uint32_t sb_ = sm + (stg) * STAGEB;                                \
        _Pragma("unroll")                                                        \
        for (int i_ = 0; i_ < 2; i_++) {  /* A: 128 rows x 4 kc = 512 */         \
            int idx_ = i_ * 256 + tid;                                           \
            int row_ = idx_ >> 2, kc_ = idx_ & 3;                                \
            uint32_t d_ = swz(row_, kc_);                                        \
            cp16(sb_ + d_, (const char*)(ah_ + (size_t)(m0 + row_) * lda + ka_) + kc_ * 16); \
        }                                                                        \
        if (MODE == 1) {                                                         \
            /* B tile: 32 e-rows x 256B ([e][d] slice), 512 chunks */            \
            _Pragma("unroll")                                                    \
            for (int i_ = 0; i_ < 2; i_++) {                                     \
                int idx_ = i_ * 256 + tid;                                       \
                int row_ = idx_ >> 4, kc_ = idx_ & 15;                           \
                uint32_t d_ = (uint32_t)(row_ * 256 + ((kc_ ^ (row_ & 7)) << 4));\
                cp16(sb_ + OFFBH + d_, (const char*)(Bh + (size_t)(k0_ + row_) * ldb + n0) + kc_ * 16); \
            }                                                                    \
        } else {                                                                 \
            /* B tile: 128 n-rows x 4 kc = 512 chunks */                         \
            _Pragma("unroll")                                                    \
            for (int i_ = 0; i_ < 2; i_++) {                                     \
                int idx_ = i_ * 256 + tid;                                       \
                int row_ = idx_ >> 2, kc_ = idx_ & 3;                            \
                uint32_t d_ = swz(row_, kc_);                                    \
                cp16(sb_ + OFFBH + d_, (const char*)(Bh + (size_t)(n0 + row_) * ldb + k0_) + kc_ * 16); \
            }                                                                    \
        }                                                                        \
    } while (0)

    // ---- per-lane ldmatrix address precomputes
    const int ar = lane & 15, ktop = lane >> 4;
    int aoff[4], axr[4];
#pragma unroll
    for (int mi = 0; mi < 4; mi++) {
        int row = wm * 64 + mi * 16 + ar;
        aoff[mi] = row * 64; axr[mi] = (row >> 1) & 3;
    }
    // NT B path (MODE 0/2): 2 groups of 16 n-rows per warp
    const int brl = ((lane >> 4) << 3) + (lane & 7);
    const int bk2 = (lane >> 3) & 1;
    int boff[2], bxr[2];
#pragma unroll
    for (int g = 0; g < 2; g++) {
        int nrow = wn * 32 + g * 16 + brl;
        boff[g] = nrow * 64; bxr[g] = (nrow >> 1) & 3;
    }
    // trans B path (MODE 1)
    const int tmt = lane >> 3, trl = lane & 7;
    const int te_base = ((tmt & 1) << 3) + trl;   // e-row within k16 group
    const int tkc_part = tmt >> 1;                // n8 selector

    float acc[4][4][4];
#pragma unroll
    for (int i = 0; i < 4; i++)
#pragma unroll
        for (int j = 0; j < 4; j++)
#pragma unroll
            for (int q = 0; q < 4; q++) acc[i][j][q] = 0.f;

    LOAD_CHUNK(0, 0); CP_COMMIT();
    LOAD_CHUNK(1, 1); CP_COMMIT();

    for (int c = 0; c < C; c++) {
        CP_WAIT1();
        __syncthreads();
        if (c + 2 < C) { LOAD_CHUNK(c + 2, (c + 2) % NSTAGE); }
        CP_COMMIT();
        const uint32_t sb = sm + (c % NSTAGE) * STAGEB;
#pragma unroll
        for (int ks = 0; ks < 2; ks++) {
            const int kb = ks * 2;
            uint32_t afr[4][4];
#pragma unroll
            for (int mi = 0; mi < 4; mi++)
                ldm4(afr[mi], sb + aoff[mi] + (((kb + ktop) ^ axr[mi]) << 4));
#pragma unroll
            for (int g = 0; g < 2; g++) {
                uint32_t bh[4];
                if (MODE == 1) {
                    const int e_r = ks * 16 + te_base;
                    const int kc = wn * 4 + g * 2 + tkc_part;
                    ldm4t(bh, sb + OFFBH + e_r * 256 + ((kc ^ trl) << 4));
                } else {
                    ldm4(bh, sb + OFFBH + boff[g] + (((kb + bk2) ^ bxr[g]) << 4));
                }
#pragma unroll
                for (int half = 0; half < 2; half++)
#pragma unroll
                    for (int mi = 0; mi < 4; mi++)
                        mma16816(acc[mi][g * 2 + half], afr[mi], &bh[half * 2]);
            }
        }
    }
#undef LOAD_CHUNK

    // ---- epilogue from registers
    const int qr = lane >> 2, qc = lane & 3;
#pragma unroll
    for (int mi = 0; mi < 4; mi++)
#pragma unroll
        for (int nj = 0; nj < 4; nj++)
#pragma unroll
            for (int half = 0; half < 2; half++) {
                const int row = m0 + wm * 64 + mi * 16 + qr + half * 8;
                const int col = n0 + wn * 32 + nj * 8 + qc * 2;
                const float v0 = acc[mi][nj][half * 2 + 0];
                const float v1 = acc[mi][nj][half * 2 + 1];
                if (MODE == 0) {
                    float2 o = make_float2(v0 * alpha, v1 * alpha);
                    *(float2*)(Cf + (size_t)b * SEQ * SEQ + (size_t)row * SEQ + col) = o;
                } else if (MODE == 1) {
                    __half2 H;
                    H.x = __float2half_rn(v0);
                    H.y = __float2half_rn(v1);
                    *(__half2*)(g_ch + (size_t)b * SB + (size_t)row * DIM + col) = H;
                } else {
                    const float mk = mask[row];
                    float2 o = make_float2(tanhf(v0 + bias[col]) * mk,
                                           tanhf(v1 + bias[col + 1]) * mk);
                    *(float2*)(Cf + (size_t)row * DIM + col) = o;
                }
            }
}

// ------ fp32 -> fp16 convert: Q, W, Enc fused in one grid (x4 vec) ----------
#define NQ4 (NELEM / 4)
#define NW4 (WELEM / 4)
#define NE4 (NELEM / 4)
__global__ __launch_bounds__(256) void k_split_all(const float4* __restrict__ Qs,
                                                   const float4* __restrict__ Ws,
                                                   const float4* __restrict__ Es)
{
    int i = blockIdx.x * 256 + threadIdx.x;
    const float4* src;
    uint2* hi;
    int j;
    if (i < NQ4) { src = Qs; hi = (uint2*)g_qh; j = i; }
    else if (i < NQ4 + NW4) { src = Ws; hi = (uint2*)g_wh; j = i - NQ4; }
    else if (i < NQ4 + NW4 + NE4) { src = Es; hi = (uint2*)g_eh; j = i - NQ4 - NW4; }
    else return;
    float4 v = src[j];
    union { __half h[4]; uint2 u; } H;
    H.h[0] = __float2half_rn(v.x);
    H.h[1] = __float2half_rn(v.y);
    H.h[2] = __float2half_rn(v.z);
    H.h[3] = __float2half_rn(v.w);
    hi[j] = H.u;
}

// ---------- softmax (in place, float4) + fp16 out ---------------------------
// 2 rows per block, 128 threads/row, 4 elements/thread.
__global__ __launch_bounds__(256) void k_softmax_split(float* __restrict__ w)
{
    const int g = threadIdx.x >> 7;
    const int r = threadIdx.x & 127;
    const size_t rowid = (size_t)blockIdx.x * 2 + g;
    float4* row = (float4*)(w + rowid * SEQ);
    float4 v = row[r];

    __shared__ float red[2][4];
    const int wl = (threadIdx.x >> 5) & 3;

    float m = fmaxf(fmaxf(v.x, v.y), fmaxf(v.z, v.w));
#pragma unroll
    for (int o = 16; o > 0; o >>= 1) m = fmaxf(m, __shfl_xor_sync(0xffffffffu, m, o));
    if ((threadIdx.x & 31) == 0) red[g][wl] = m;
    __syncthreads();
    const float M = fmaxf(fmaxf(red[g][0], red[g][1]), fmaxf(red[g][2], red[g][3]));
    __syncthreads();

    float4 e;
    e.x = __expf(v.x - M); e.y = __expf(v.y - M);
    e.z = __expf(v.z - M); e.w = __expf(v.w - M);
    float s = e.x + e.y + e.z + e.w;
#pragma unroll
    for (int o = 16; o > 0; o >>= 1) s += __shfl_xor_sync(0xffffffffu, s, o);
    if ((threadIdx.x & 31) == 0) red[g][wl] = s;
    __syncthreads();
    const float S = red[g][0] + red[g][1] + red[g][2] + red[g][3];
    const float inv = 1.0f / S;

    e.x *= inv; e.y *= inv; e.z *= inv; e.w *= inv;
    row[r] = e;

    union { __half h[4]; uint2 u; } H;
    H.h[0] = __float2half_rn(e.x);
    H.h[1] = __float2half_rn(e.y);
    H.h[2] = __float2half_rn(e.z);
    H.h[3] = __float2half_rn(e.w);
    ((uint2*)(g_awh + rowid * SEQ))[r] = H.u;
}

// ---------------------------------------------------------------------------
extern "C" void kernel_launch(void* const* d_in, const int* in_sizes, int n_in,
                              void* d_out, int out_size)
{
    const float* Q    = (const float*)d_in[0];
    const float* Enc  = (const float*)d_in[1];
    const float* mask = (const float*)d_in[2];
    const float* W    = (const float*)d_in[3];
    const float* bias = (const float*)d_in[4];

    float* out_masked  = (float*)d_out;
    float* out_weights = (float*)d_out + NELEM;

    static bool attr_done = false;
    if (!attr_done) {
        cudaFuncSetAttribute(k_gemm<0>, cudaFuncAttributeMaxDynamicSharedMemorySize, SMEM_DYN);
        cudaFuncSetAttribute(k_gemm<1>, cudaFuncAttributeMaxDynamicSharedMemorySize, SMEM_DYN);
        cudaFuncSetAttribute(k_gemm<2>, cudaFuncAttributeMaxDynamicSharedMemorySize, SMEM_DYN);
        attr_done = true;
    }

    const float alpha = 1.0f / sqrtf((float)DIM);

    // 1) one fused convert kernel (Q, W, Enc -> fp16)
    {
        int total = (int)(NQ4 + NW4 + NE4);
        k_split_all<<<(total + 255) / 256, 256>>>((const float4*)Q, (const float4*)W,
                                                  (const float4*)Enc);
    }
    // 2) scores = alpha * Q @ Enc^T -> out_weights (fp32)
    {
        dim3 g(SEQ / 128, SEQ / 128, BATCH);
        k_gemm<0><<<g, 256, SMEM_DYN>>>(out_weights, nullptr, nullptr, alpha);
    }
    // 3) softmax + fp16
    k_softmax_split<<<BATCH * SEQ / 2, 256>>>(out_weights);
    // 4) ctx = AW @ Enc (trans-B) -> g_ch (fp16)
    {
        dim3 g(DIM / 128, SEQ / 128, BATCH);
        k_gemm<1><<<g, 256, SMEM_DYN>>>(nullptr, nullptr, nullptr, 1.0f);
    }
    // 5) out = tanh([Q|ctx] @ W^T + bias) * mask
    {
        dim3 g(DIM / 128, (BATCH * SEQ) / 128, 1);
        k_gemm<2><<<g, 256, SMEM_DYN>>>(out_masked, bias, mask, 1.0f);
    }
}

// round 15
// speedup vs baseline: 1.0750x; 1.0750x over previous
#include <cuda_runtime.h>
#include <cuda_fp16.h>
#include <cstdint>
#include <math.h>

#define BATCH 32
#define SEQ   512
#define DIM   512

// ---------------- scratch (static device memory; no allocations) ------------
#define NELEM ((size_t)BATCH * SEQ * DIM)          // 8,388,608
#define WELEM ((size_t)DIM * 2 * DIM)              // 524,288
__device__ __align__(16) __half g_qh[NELEM];                // Q fp16       [b,q,d]
__device__ __align__(16) __half g_eh[NELEM];                // Enc fp16     [b,e,d]
__device__ __align__(16) __half g_awh[NELEM];               // attn weights [b,q,e]
__device__ __align__(16) __half g_ch[NELEM];                // ctx fp16     [b,q,d]
__device__ __align__(16) __half g_wh[WELEM];                // W fp16

// ---------------- PTX helpers (all non-arch-'a'; compile for sm_103) --------
__device__ __forceinline__ uint32_t smem_u32(const void* p) {
    uint32_t a;
    asm("{ .reg .u64 t; cvta.to.shared.u64 t, %1; cvt.u32.u64 %0, t; }" : "=r"(a) : "l"(p));
    return a;
}
__device__ __forceinline__ void cp16(uint32_t dst, const void* src) {
    asm volatile("cp.async.cg.shared.global [%0], [%1], 16;" :: "r"(dst), "l"(src));
}
#define CP_COMMIT() asm volatile("cp.async.commit_group;" ::: "memory")
#define CP_WAIT1()  asm volatile("cp.async.wait_group 1;" ::: "memory")

__device__ __forceinline__ void ldm4(uint32_t* r, uint32_t addr) {
    asm volatile("ldmatrix.sync.aligned.m8n8.x4.shared.b16 {%0,%1,%2,%3}, [%4];"
                 : "=r"(r[0]), "=r"(r[1]), "=r"(r[2]), "=r"(r[3]) : "r"(addr));
}
__device__ __forceinline__ void ldm4t(uint32_t* r, uint32_t addr) {
    asm volatile("ldmatrix.sync.aligned.m8n8.x4.trans.shared.b16 {%0,%1,%2,%3}, [%4];"
                 : "=r"(r[0]), "=r"(r[1]), "=r"(r[2]), "=r"(r[3]) : "r"(addr));
}
__device__ __forceinline__ void mma16816(float* c, const uint32_t* a, const uint32_t* b) {
    asm volatile(
        "mma.sync.aligned.m16n8k16.row.col.f32.f16.f16.f32 "
        "{%0,%1,%2,%3}, {%4,%5,%6,%7}, {%8,%9}, {%0,%1,%2,%3};"
        : "+f"(c[0]), "+f"(c[1]), "+f"(c[2]), "+f"(c[3])
        : "r"(a[0]), "r"(a[1]), "r"(a[2]), "r"(a[3]), "r"(b[0]), "r"(b[1]));
}

// ---------------- GEMM: C = A @ B^T, fp16 1-term, BK=64 ----------------------
// CTA tile 128(m) x 64(n), BK=64 (128B rows). 8 warps = 4m x 2n, warp 32x32.
// smem/stage: A 16KB + B 8KB = 24KB; 3 stages = 72KB; 3 CTAs/SM (216KB).
// Half the barriers of BK=32 (8 chunks for K=512).
#define TILE_A   16384          // 128 rows x 128B
#define TILE_BB  8192           // 64 rows x 128B
#define OFFBH    TILE_A
#define STAGEB   (TILE_A + TILE_BB)   // 24KB
#define NSTAGE   3
#define SMEM_DYN (NSTAGE * STAGEB)
#define SB ((size_t)SEQ * DIM)

// swizzled byte offset within a 128B-row tile for (row, 16B-chunk kc 0..7)
__device__ __forceinline__ uint32_t swz128(int row, int kc) {
    return (uint32_t)(row * 128 + ((kc ^ (row & 7)) << 4));
}

// MODE 0: scores = alpha * Q @ Enc^T          -> Cf (fp32)
// MODE 1: ctx    = AW @ Enc  (trans-B)        -> g_ch (fp16)
// MODE 2: out    = tanh([Q|ctx] @ W^T + b)*m  -> Cf (fp32)
template <int MODE>
__global__ __launch_bounds__(256, 3) void k_gemm(
    float* __restrict__ Cf, const float* __restrict__ bias,
    const float* __restrict__ mask, float alpha)
{
    extern __shared__ char smem[];
    const uint32_t sm = smem_u32(smem);

    const int tid = threadIdx.x;
    const int lane = tid & 31, wid = tid >> 5;
    const int wm = wid & 3, wn = wid >> 2;       // 4 m-warps x 2 n-warps
    const int b  = blockIdx.z;
    const int m0 = blockIdx.y * 128;
    const int n0 = blockIdx.x * 64;

    const __half *Ah, *A2h = nullptr, *Bh;
    int K, lda, ldb;
    if (MODE == 0) {
        Ah = g_qh + (size_t)b * SB;
        Bh = g_eh + (size_t)b * SB;
        K = DIM; lda = DIM; ldb = DIM;
    } else if (MODE == 1) {
        Ah = g_awh + (size_t)b * SB;
        Bh = g_eh + (size_t)b * SB;                                // [e][d] plain
        K = SEQ; lda = SEQ; ldb = DIM;
    } else {
        Ah = g_qh;  A2h = g_ch;      // rows indexed by global m (0..16383)
        Bh = g_wh;
        K = 2 * DIM; lda = DIM; ldb = 2 * DIM;
    }
    const int C = K >> 6;   // chunks of 64

#define LOAD_CHUNK(c, stg)                                                       \
    do {                                                                         \
        const int k0_ = (c) * 64;                                                \
        const __half* ah_; int ka_;                                              \
        if (MODE == 2 && k0_ >= DIM) { ah_ = A2h; ka_ = k0_ - DIM; }             \
        else                         { ah_ = Ah;  ka_ = k0_; }                   \
        const uint32_t sb_ = sm + (stg) * STAGEB;                                \
        _Pragma("unroll")                                                        \
        for (int i_ = 0; i_ < 4; i_++) {  /* A: 128 rows x 8 kc = 1024 */        \
            int idx_ = i_ * 256 + tid;                                           \
            int row_ = idx_ >> 3, kc_ = idx_ & 7;                                \
            uint32_t d_ = swz128(row_, kc_);                                     \
            cp16(sb_ + d_, (const char*)(ah_ + (size_t)(m0 + row_) * lda + ka_) + kc_ * 16); \
        }                                                                        \
        _Pragma("unroll")                                                        \
        for (int i_ = 0; i_ < 2; i_++) {  /* B: 64 rows x 8 kc = 512 */          \
            int idx_ = i_ * 256 + tid;                                           \
            int row_ = idx_ >> 3, kc_ = idx_ & 7;                                \
            uint32_t d_ = swz128(row_, kc_);                                     \
            const char* pb_ = (MODE == 1)                                        \
                ? (const char*)(Bh + (size_t)(k0_ + row_) * ldb + n0) + kc_ * 16 \
                : (const char*)(Bh + (size_t)(n0 + row_) * ldb + k0_) + kc_ * 16;\
            cp16(sb_ + OFFBH + d_, pb_);                                         \
        }                                                                        \
    } while (0)

    // ---- per-lane ldmatrix address precomputes
    const int ar = lane & 15, ktop = lane >> 4;
    int aoff[2], axr[2];
#pragma unroll
    for (int mi = 0; mi < 2; mi++) {
        int row = wm * 32 + mi * 16 + ar;
        aoff[mi] = row * 128; axr[mi] = row & 7;
    }
    // NT B path (MODE 0/2): 2 groups of 16 n-rows per warp
    const int brl = ((lane >> 4) << 3) + (lane & 7);
    const int bk2 = (lane >> 3) & 1;
    int boff[2], bxr[2];
#pragma unroll
    for (int g = 0; g < 2; g++) {
        int nrow = wn * 32 + g * 16 + brl;
        boff[g] = nrow * 128; bxr[g] = nrow & 7;
    }
    // trans B path (MODE 1)
    const int tmt = lane >> 3, trl = lane & 7;
    const int te_base = ((tmt & 1) << 3) + trl;   // e-row within k16 group
    const int tkc_part = tmt >> 1;                // n8 selector

    float acc[2][4][4];
#pragma unroll
    for (int i = 0; i < 2; i++)
#pragma unroll
        for (int j = 0; j < 4; j++)
#pragma unroll
            for (int q = 0; q < 4; q++) acc[i][j][q] = 0.f;

    LOAD_CHUNK(0, 0); CP_COMMIT();
    LOAD_CHUNK(1, 1); CP_COMMIT();

    for (int c = 0; c < C; c++) {
        CP_WAIT1();
        __syncthreads();
        if (c + 2 < C) { LOAD_CHUNK(c + 2, (c + 2) % NSTAGE); }
        CP_COMMIT();
        const uint32_t sb = sm + (c % NSTAGE) * STAGEB;
#pragma unroll
        for (int ks = 0; ks < 4; ks++) {
            const int kb = ks * 2;
            uint32_t afr[2][4];
#pragma unroll
            for (int mi = 0; mi < 2; mi++)
                ldm4(afr[mi], sb + aoff[mi] + (((kb + ktop) ^ axr[mi]) << 4));
#pragma unroll
            for (int g = 0; g < 2; g++) {
                uint32_t bh[4];
                if (MODE == 1) {
                    const int e_r = ks * 16 + te_base;       // 0..63
                    const int kc = wn * 4 + g * 2 + tkc_part; // 0..7
                    ldm4t(bh, sb + OFFBH + e_r * 128 + ((kc ^ trl) << 4));
                } else {
                    ldm4(bh, sb + OFFBH + boff[g] + (((kb + bk2) ^ bxr[g]) << 4));
                }
#pragma unroll
                for (int half = 0; half < 2; half++)
#pragma unroll
                    for (int mi = 0; mi < 2; mi++)
                        mma16816(acc[mi][g * 2 + half], afr[mi], &bh[half * 2]);
            }
        }
    }
#undef LOAD_CHUNK

    // ---- epilogue from registers
    const int qr = lane >> 2, qc = lane & 3;
#pragma unroll
    for (int mi = 0; mi < 2; mi++)
#pragma unroll
        for (int nj = 0; nj < 4; nj++)
#pragma unroll
            for (int half = 0; half < 2; half++) {
                const int row = m0 + wm * 32 + mi * 16 + qr + half * 8;
                const int col = n0 + wn * 32 + nj * 8 + qc * 2;
                const float v0 = acc[mi][nj][half * 2 + 0];
                const float v1 = acc[mi][nj][half * 2 + 1];
                if (MODE == 0) {
                    float2 o = make_float2(v0 * alpha, v1 * alpha);
                    *(float2*)(Cf + (size_t)b * SEQ * SEQ + (size_t)row * SEQ + col) = o;
                } else if (MODE == 1) {
                    __half2 H;
                    H.x = __float2half_rn(v0);
                    H.y = __float2half_rn(v1);
                    *(__half2*)(g_ch + (size_t)b * SB + (size_t)row * DIM + col) = H;
                } else {
                    const float mk = mask[row];
                    float2 o = make_float2(tanhf(v0 + bias[col]) * mk,
                                           tanhf(v1 + bias[col + 1]) * mk);
                    *(float2*)(Cf + (size_t)row * DIM + col) = o;
                }
            }
}

// ------ fp32 -> fp16 convert: Q, W, Enc fused in one grid (x4 vec) ----------
#define NQ4 (NELEM / 4)
#define NW4 (WELEM / 4)
#define NE4 (NELEM / 4)
__global__ __launch_bounds__(256) void k_split_all(const float4* __restrict__ Qs,
                                                   const float4* __restrict__ Ws,
                                                   const float4* __restrict__ Es)
{
    int i = blockIdx.x * 256 + threadIdx.x;
    const float4* src;
    uint2* hi;
    int j;
    if (i < NQ4) { src = Qs; hi = (uint2*)g_qh; j = i; }
    else if (i < NQ4 + NW4) { src = Ws; hi = (uint2*)g_wh; j = i - NQ4; }
    else if (i < NQ4 + NW4 + NE4) { src = Es; hi = (uint2*)g_eh; j = i - NQ4 - NW4; }
    else return;
    float4 v = src[j];
    union { __half h[4]; uint2 u; } H;
    H.h[0] = __float2half_rn(v.x);
    H.h[1] = __float2half_rn(v.y);
    H.h[2] = __float2half_rn(v.z);
    H.h[3] = __float2half_rn(v.w);
    hi[j] = H.u;
}

// ---------- softmax (in place, float4) + fp16 out ---------------------------
// 2 rows per block, 128 threads/row, 4 elements/thread.
__global__ __launch_bounds__(256) void k_softmax_split(float* __restrict__ w)
{
    const int g = threadIdx.x >> 7;
    const int r = threadIdx.x & 127;
    const size_t rowid = (size_t)blockIdx.x * 2 + g;
    float4* row = (float4*)(w + rowid * SEQ);
    float4 v = row[r];

    __shared__ float red[2][4];
    const int wl = (threadIdx.x >> 5) & 3;

    float m = fmaxf(fmaxf(v.x, v.y), fmaxf(v.z, v.w));
#pragma unroll
    for (int o = 16; o > 0; o >>= 1) m = fmaxf(m, __shfl_xor_sync(0xffffffffu, m, o));
    if ((threadIdx.x & 31) == 0) red[g][wl] = m;
    __syncthreads();
    const float M = fmaxf(fmaxf(red[g][0], red[g][1]), fmaxf(red[g][2], red[g][3]));
    __syncthreads();

    float4 e;
    e.x = __expf(v.x - M); e.y = __expf(v.y - M);
    e.z = __expf(v.z - M); e.w = __expf(v.w - M);
    float s = e.x + e.y + e.z + e.w;
#pragma unroll
    for (int o = 16; o > 0; o >>= 1) s += __shfl_xor_sync(0xffffffffu, s, o);
    if ((threadIdx.x & 31) == 0) red[g][wl] = s;
    __syncthreads();
    const float S = red[g][0] + red[g][1] + red[g][2] + red[g][3];
    const float inv = 1.0f / S;

    e.x *= inv; e.y *= inv; e.z *= inv; e.w *= inv;
    row[r] = e;

    union { __half h[4]; uint2 u; } H;
    H.h[0] = __float2half_rn(e.x);
    H.h[1] = __float2half_rn(e.y);
    H.h[2] = __float2half_rn(e.z);
    H.h[3] = __float2half_rn(e.w);
    ((uint2*)(g_awh + rowid * SEQ))[r] = H.u;
}

// ---------------------------------------------------------------------------
extern "C" void kernel_launch(void* const* d_in, const int* in_sizes, int n_in,
                              void* d_out, int out_size)
{
    const float* Q    = (const float*)d_in[0];
    const float* Enc  = (const float*)d_in[1];
    const float* mask = (const float*)d_in[2];
    const float* W    = (const float*)d_in[3];
    const float* bias = (const float*)d_in[4];

    float* out_masked  = (float*)d_out;
    float* out_weights = (float*)d_out + NELEM;

    static bool attr_done = false;
    if (!attr_done) {
        cudaFuncSetAttribute(k_gemm<0>, cudaFuncAttributeMaxDynamicSharedMemorySize, SMEM_DYN);
        cudaFuncSetAttribute(k_gemm<1>, cudaFuncAttributeMaxDynamicSharedMemorySize, SMEM_DYN);
        cudaFuncSetAttribute(k_gemm<2>, cudaFuncAttributeMaxDynamicSharedMemorySize, SMEM_DYN);
        attr_done = true;
    }

    const float alpha = 1.0f / sqrtf((float)DIM);

    // 1) one fused convert kernel (Q, W, Enc -> fp16)
    {
        int total = (int)(NQ4 + NW4 + NE4);
        k_split_all<<<(total + 255) / 256, 256>>>((const float4*)Q, (const float4*)W,
                                                  (const float4*)Enc);
    }
    // 2) scores = alpha * Q @ Enc^T -> out_weights (fp32)
    {
        dim3 g(SEQ / 64, SEQ / 128, BATCH);
        k_gemm<0><<<g, 256, SMEM_DYN>>>(out_weights, nullptr, nullptr, alpha);
    }
    // 3) softmax + fp16
    k_softmax_split<<<BATCH * SEQ / 2, 256>>>(out_weights);
    // 4) ctx = AW @ Enc (trans-B) -> g_ch (fp16)
    {
        dim3 g(DIM / 64, SEQ / 128, BATCH);
        k_gemm<1><<<g, 256, SMEM_DYN>>>(nullptr, nullptr, nullptr, 1.0f);
    }
    // 5) out = tanh([Q|ctx] @ W^T + bias) * mask
    {
        dim3 g(DIM / 64, (BATCH * SEQ) / 128, 1);
        k_gemm<2><<<g, 256, SMEM_DYN>>>(out_masked, bias, mask, 1.0f);
    }
}

// round 16
// speedup vs baseline: 1.0897x; 1.0137x over previous
#include <cuda_runtime.h>
#include <cuda_fp16.h>
#include <cstdint>
#include <math.h>

#define BATCH 32
#define SEQ   512
#define DIM   512

// ---------------- scratch (static device memory; no allocations) ------------
#define NELEM ((size_t)BATCH * SEQ * DIM)          // 8,388,608
#define WELEM ((size_t)DIM * 2 * DIM)              // 524,288
__device__ __align__(16) __half g_qh[NELEM];                // Q fp16       [b,q,d]
__device__ __align__(16) __half g_eh[NELEM];                // Enc fp16     [b,e,d]
__device__ __align__(16) __half g_sc[NELEM];                // raw scores   [b,q,e]
__device__ __align__(16) __half g_awh[NELEM];               // attn weights [b,q,e]
__device__ __align__(16) __half g_ch[NELEM];                // ctx fp16     [b,q,d]
__device__ __align__(16) __half g_wh[WELEM];                // W fp16

// ---------------- PTX helpers (all non-arch-'a'; compile for sm_103) --------
__device__ __forceinline__ uint32_t smem_u32(const void* p) {
    uint32_t a;
    asm("{ .reg .u64 t; cvta.to.shared.u64 t, %1; cvt.u32.u64 %0, t; }" : "=r"(a) : "l"(p));
    return a;
}
__device__ __forceinline__ void cp16(uint32_t dst, const void* src) {
    asm volatile("cp.async.cg.shared.global [%0], [%1], 16;" :: "r"(dst), "l"(src));
}
#define CP_COMMIT() asm volatile("cp.async.commit_group;" ::: "memory")
#define CP_WAIT1()  asm volatile("cp.async.wait_group 1;" ::: "memory")

__device__ __forceinline__ void ldm4(uint32_t* r, uint32_t addr) {
    asm volatile("ldmatrix.sync.aligned.m8n8.x4.shared.b16 {%0,%1,%2,%3}, [%4];"
                 : "=r"(r[0]), "=r"(r[1]), "=r"(r[2]), "=r"(r[3]) : "r"(addr));
}
__device__ __forceinline__ void ldm4t(uint32_t* r, uint32_t addr) {
    asm volatile("ldmatrix.sync.aligned.m8n8.x4.trans.shared.b16 {%0,%1,%2,%3}, [%4];"
                 : "=r"(r[0]), "=r"(r[1]), "=r"(r[2]), "=r"(r[3]) : "r"(addr));
}
__device__ __forceinline__ void mma16816(float* c, const uint32_t* a, const uint32_t* b) {
    asm volatile(
        "mma.sync.aligned.m16n8k16.row.col.f32.f16.f16.f32 "
        "{%0,%1,%2,%3}, {%4,%5,%6,%7}, {%8,%9}, {%0,%1,%2,%3};"
        : "+f"(c[0]), "+f"(c[1]), "+f"(c[2]), "+f"(c[3])
        : "r"(a[0]), "r"(a[1]), "r"(a[2]), "r"(a[3]), "r"(b[0]), "r"(b[1]));
}

// ---------------- GEMM: C = A @ B^T, fp16 1-term (R13 geometry) --------------
// CTA tile 128(m) x 64(n), BK=32. 8 warps = 4m x 2n, warp tile 32x32.
// smem/stage: A 8KB + B 4KB = 12KB; 3 stages = 36KB; 3 CTAs/SM.
#define TILE_A   8192           // 128 rows x 64B
#define TILE_BB  4096           // 64 rows x 64B (or 32 rows x 128B for MODE1)
#define OFFBH    TILE_A
#define STAGEB   (TILE_A + TILE_BB)   // 12KB
#define NSTAGE   3
#define SMEM_DYN (NSTAGE * STAGEB)
#define SB ((size_t)SEQ * DIM)

// swizzled byte offset within one NT tile for (row, 16B-chunk kc), 64B rows
__device__ __forceinline__ uint32_t swz(int row, int kc) {
    return (uint32_t)(row * 64 + ((kc ^ ((row >> 1) & 3)) << 4));
}

// MODE 0: raw scores = alpha * Q @ Enc^T      -> g_sc (fp16)
// MODE 1: ctx    = AW @ Enc  (trans-B)        -> g_ch (fp16)
// MODE 2: out    = tanh([Q|ctx] @ W^T + b)*m  -> Cf (fp32)
template <int MODE>
__global__ __launch_bounds__(256, 3) void k_gemm(
    float* __restrict__ Cf, const float* __restrict__ bias,
    const float* __restrict__ mask, float alpha)
{
    extern __shared__ char smem[];
    const uint32_t sm = smem_u32(smem);

    const int tid = threadIdx.x;
    const int lane = tid & 31, wid = tid >> 5;
    const int wm = wid & 3, wn = wid >> 2;       // 4 m-warps x 2 n-warps
    const int b  = blockIdx.z;
    const int m0 = blockIdx.y * 128;
    const int n0 = blockIdx.x * 64;

    const __half *Ah, *A2h = nullptr, *Bh;
    int K, lda, ldb;
    if (MODE == 0) {
        Ah = g_qh + (size_t)b * SB;
        Bh = g_eh + (size_t)b * SB;
        K = DIM; lda = DIM; ldb = DIM;
    } else if (MODE == 1) {
        Ah = g_awh + (size_t)b * SB;
        Bh = g_eh + (size_t)b * SB;                                // [e][d] plain
        K = SEQ; lda = SEQ; ldb = DIM;
    } else {
        Ah = g_qh;  A2h = g_ch;      // rows indexed by global m (0..16383)
        Bh = g_wh;
        K = 2 * DIM; lda = DIM; ldb = 2 * DIM;
    }
    const int C = K >> 5;   // chunks of 32

#define LOAD_CHUNK(c, stg)                                                       \
    do {                                                                         \
        const int k0_ = (c) * 32;                                                \
        const __half* ah_; int ka_;                                              \
        if (MODE == 2 && k0_ >= DIM) { ah_ = A2h; ka_ = k0_ - DIM; }             \
        else                         { ah_ = Ah;  ka_ = k0_; }                   \
        const uint32_t sb_ = sm + (stg) * STAGEB;                                \
        _Pragma("unroll")                                                        \
        for (int i_ = 0; i_ < 2; i_++) {  /* A: 128 rows x 4 kc = 512 */         \
            int idx_ = i_ * 256 + tid;                                           \
            int row_ = idx_ >> 2, kc_ = idx_ & 3;                                \
            uint32_t d_ = swz(row_, kc_);                                        \
            cp16(sb_ + d_, (const char*)(ah_ + (size_t)(m0 + row_) * lda + ka_) + kc_ * 16); \
        }                                                                        \
        if (MODE == 1) {                                                         \
            /* B tile: 32 e-rows x 128B ([e][d] slice), 256 chunks */            \
            int row_ = tid >> 3, kc_ = tid & 7;                                  \
            uint32_t d_ = (uint32_t)(row_ * 128 + ((kc_ ^ (row_ & 7)) << 4));    \
            cp16(sb_ + OFFBH + d_, (const char*)(Bh + (size_t)(k0_ + row_) * ldb + n0) + kc_ * 16); \
        } else {                                                                 \
            /* B tile: 64 n-rows x 4 kc = 256 chunks */                          \
            int row_ = tid >> 2, kc_ = tid & 3;                                  \
            uint32_t d_ = swz(row_, kc_);                                        \
            cp16(sb_ + OFFBH + d_, (const char*)(Bh + (size_t)(n0 + row_) * ldb + k0_) + kc_ * 16); \
        }                                                                        \
    } while (0)

    // ---- per-lane ldmatrix address precomputes
    const int ar = lane & 15, ktop = lane >> 4;
    int aoff[2], axr[2];
#pragma unroll
    for (int mi = 0; mi < 2; mi++) {
        int row = wm * 32 + mi * 16 + ar;
        aoff[mi] = row * 64; axr[mi] = (row >> 1) & 3;
    }
    // NT B path (MODE 0/2): 2 groups of 16 n-rows per warp
    const int brl = ((lane >> 4) << 3) + (lane & 7);
    const int bk2 = (lane >> 3) & 1;
    int boff[2], bxr[2];
#pragma unroll
    for (int g = 0; g < 2; g++) {
        int nrow = wn * 32 + g * 16 + brl;
        boff[g] = nrow * 64; bxr[g] = (nrow >> 1) & 3;
    }
    // trans B path (MODE 1)
    const int tmt = lane >> 3, trl = lane & 7;
    const int te_base = ((tmt & 1) << 3) + trl;   // e-row within k16 group
    const int tkc_part = tmt >> 1;                // n8 selector

    float acc[2][4][4];
#pragma unroll
    for (int i = 0; i < 2; i++)
#pragma unroll
        for (int j = 0; j < 4; j++)
#pragma unroll
            for (int q = 0; q < 4; q++) acc[i][j][q] = 0.f;

    LOAD_CHUNK(0, 0); CP_COMMIT();
    LOAD_CHUNK(1, 1); CP_COMMIT();

    for (int c = 0; c < C; c++) {
        CP_WAIT1();
        __syncthreads();
        if (c + 2 < C) { LOAD_CHUNK(c + 2, (c + 2) % NSTAGE); }
        CP_COMMIT();
        const uint32_t sb = sm + (c % NSTAGE) * STAGEB;
#pragma unroll
        for (int ks = 0; ks < 2; ks++) {
            const int kb = ks * 2;
            uint32_t afr[2][4];
#pragma unroll
            for (int mi = 0; mi < 2; mi++)
                ldm4(afr[mi], sb + aoff[mi] + (((kb + ktop) ^ axr[mi]) << 4));
#pragma unroll
            for (int g = 0; g < 2; g++) {
                uint32_t bh[4];
                if (MODE == 1) {
                    const int e_r = ks * 16 + te_base;
                    const int kc = wn * 4 + g * 2 + tkc_part;
                    ldm4t(bh, sb + OFFBH + e_r * 128 + ((kc ^ trl) << 4));
                } else {
                    ldm4(bh, sb + OFFBH + boff[g] + (((kb + bk2) ^ bxr[g]) << 4));
                }
#pragma unroll
                for (int half = 0; half < 2; half++)
#pragma unroll
                    for (int mi = 0; mi < 2; mi++)
                        mma16816(acc[mi][g * 2 + half], afr[mi], &bh[half * 2]);
            }
        }
    }
#undef LOAD_CHUNK

    // ---- epilogue from registers
    const int qr = lane >> 2, qc = lane & 3;
#pragma unroll
    for (int mi = 0; mi < 2; mi++)
#pragma unroll
        for (int nj = 0; nj < 4; nj++)
#pragma unroll
            for (int half = 0; half < 2; half++) {
                const int row = m0 + wm * 32 + mi * 16 + qr + half * 8;
                const int col = n0 + wn * 32 + nj * 8 + qc * 2;
                const float v0 = acc[mi][nj][half * 2 + 0];
                const float v1 = acc[mi][nj][half * 2 + 1];
                if (MODE == 0) {
                    __half2 H;
                    H.x = __float2half_rn(v0 * alpha);
                    H.y = __float2half_rn(v1 * alpha);
                    *(__half2*)(g_sc + (size_t)b * SB + (size_t)row * SEQ + col) = H;
                } else if (MODE == 1) {
                    __half2 H;
                    H.x = __float2half_rn(v0);
                    H.y = __float2half_rn(v1);
                    *(__half2*)(g_ch + (size_t)b * SB + (size_t)row * DIM + col) = H;
                } else {
                    const float mk = mask[row];
                    float2 o = make_float2(tanhf(v0 + bias[col]) * mk,
                                           tanhf(v1 + bias[col + 1]) * mk);
                    *(float2*)(Cf + (size_t)row * DIM + col) = o;
                }
            }
}

// ------ fp32 -> fp16 convert: Q, W, Enc fused in one grid (x4 vec) ----------
#define NQ4 (NELEM / 4)
#define NW4 (WELEM / 4)
#define NE4 (NELEM / 4)
__global__ __launch_bounds__(256) void k_split_all(const float4* __restrict__ Qs,
                                                   const float4* __restrict__ Ws,
                                                   const float4* __restrict__ Es)
{
    int i = blockIdx.x * 256 + threadIdx.x;
    const float4* src;
    uint2* hi;
    int j;
    if (i < NQ4) { src = Qs; hi = (uint2*)g_qh; j = i; }
    else if (i < NQ4 + NW4) { src = Ws; hi = (uint2*)g_wh; j = i - NQ4; }
    else if (i < NQ4 + NW4 + NE4) { src = Es; hi = (uint2*)g_eh; j = i - NQ4 - NW4; }
    else return;
    float4 v = src[j];
    union { __half h[4]; uint2 u; } H;
    H.h[0] = __float2half_rn(v.x);
    H.h[1] = __float2half_rn(v.y);
    H.h[2] = __float2half_rn(v.z);
    H.h[3] = __float2half_rn(v.w);
    hi[j] = H.u;
}

// ---------- softmax: read fp16 raw scores -> fp32 weights + fp16 weights ----
// 2 rows per block, 128 threads/row, 4 elements/thread.
__global__ __launch_bounds__(256) void k_softmax_split(float* __restrict__ w)
{
    const int g = threadIdx.x >> 7;
    const int r = threadIdx.x & 127;
    const size_t rowid = (size_t)blockIdx.x * 2 + g;

    union { __half h[4]; uint2 u; } S;
    S.u = ((const uint2*)(g_sc + rowid * SEQ))[r];
    float4 v;
    v.x = __half2float(S.h[0]); v.y = __half2float(S.h[1]);
    v.z = __half2float(S.h[2]); v.w = __half2float(S.h[3]);

    __shared__ float red[2][4];
    const int wl = (threadIdx.x >> 5) & 3;

    float m = fmaxf(fmaxf(v.x, v.y), fmaxf(v.z, v.w));
#pragma unroll
    for (int o = 16; o > 0; o >>= 1) m = fmaxf(m, __shfl_xor_sync(0xffffffffu, m, o));
    if ((threadIdx.x & 31) == 0) red[g][wl] = m;
    __syncthreads();
    const float M = fmaxf(fmaxf(red[g][0], red[g][1]), fmaxf(red[g][2], red[g][3]));
    __syncthreads();

    float4 e;
    e.x = __expf(v.x - M); e.y = __expf(v.y - M);
    e.z = __expf(v.z - M); e.w = __expf(v.w - M);
    float s = e.x + e.y + e.z + e.w;
#pragma unroll
    for (int o = 16; o > 0; o >>= 1) s += __shfl_xor_sync(0xffffffffu, s, o);
    if ((threadIdx.x & 31) == 0) red[g][wl] = s;
    __syncthreads();
    const float S2 = red[g][0] + red[g][1] + red[g][2] + red[g][3];
    const float inv = 1.0f / S2;

    e.x *= inv; e.y *= inv; e.z *= inv; e.w *= inv;
    ((float4*)(w + rowid * SEQ))[r] = e;

    union { __half h[4]; uint2 u; } H;
    H.h[0] = __float2half_rn(e.x);
    H.h[1] = __float2half_rn(e.y);
    H.h[2] = __float2half_rn(e.z);
    H.h[3] = __float2half_rn(e.w);
    ((uint2*)(g_awh + rowid * SEQ))[r] = H.u;
}

// ---------------------------------------------------------------------------
extern "C" void kernel_launch(void* const* d_in, const int* in_sizes, int n_in,
                              void* d_out, int out_size)
{
    const float* Q    = (const float*)d_in[0];
    const float* Enc  = (const float*)d_in[1];
    const float* mask = (const float*)d_in[2];
    const float* W    = (const float*)d_in[3];
    const float* bias = (const float*)d_in[4];

    float* out_masked  = (float*)d_out;
    float* out_weights = (float*)d_out + NELEM;

    static bool attr_done = false;
    if (!attr_done) {
        cudaFuncSetAttribute(k_gemm<0>, cudaFuncAttributeMaxDynamicSharedMemorySize, SMEM_DYN);
        cudaFuncSetAttribute(k_gemm<1>, cudaFuncAttributeMaxDynamicSharedMemorySize, SMEM_DYN);
        cudaFuncSetAttribute(k_gemm<2>, cudaFuncAttributeMaxDynamicSharedMemorySize, SMEM_DYN);
        attr_done = true;
    }

    const float alpha = 1.0f / sqrtf((float)DIM);

    // 1) one fused convert kernel (Q, W, Enc -> fp16)
    {
        int total = (int)(NQ4 + NW4 + NE4);
        k_split_all<<<(total + 255) / 256, 256>>>((const float4*)Q, (const float4*)W,
                                                  (const float4*)Enc);
    }
    // 2) raw scores = alpha * Q @ Enc^T -> g_sc (fp16)
    {
        dim3 g(SEQ / 64, SEQ / 128, BATCH);
        k_gemm<0><<<g, 256, SMEM_DYN>>>(nullptr, nullptr, nullptr, alpha);
    }
    // 3) softmax: g_sc -> out_weights (fp32) + g_awh (fp16)
    k_softmax_split<<<BATCH * SEQ / 2, 256>>>(out_weights);
    // 4) ctx = AW @ Enc (trans-B) -> g_ch (fp16)
    {
        dim3 g(DIM / 64, SEQ / 128, BATCH);
        k_gemm<1><<<g, 256, SMEM_DYN>>>(nullptr, nullptr, nullptr, 1.0f);
    }
    // 5) out = tanh([Q|ctx] @ W^T + bias) * mask
    {
        dim3 g(DIM / 64, (BATCH * SEQ) / 128, 1);
        k_gemm<2><<<g, 256, SMEM_DYN>>>(out_masked, bias, mask, 1.0f);
    }
}